// round 10
// baseline (speedup 1.0000x reference)
#include <cuda_runtime.h>

// QConv1D quantum sim, R10: closed-form (Heisenberg / independent-set transfer
// matrix DP), warp-self-contained (no smem, no barriers).
//  R10 deltas vs R9: single LDG.128 weight load per lane (lane owns qubits
//  2g, 2g+1 for its o-channel), x-trig MUFU issued before weight trig so the
//  DP's first steps aren't gated on the last sincos.
constexpr int O_CH  = 8;
constexpr int NQ    = 8;
constexpr int L_IN  = 512;
constexpr int L_OUT = 509;
constexpr int B_SZ  = 16;
constexpr int N_POS = B_SZ * L_OUT;          // 8144 (multiple of 8)
constexpr int TPB   = 512;
constexpr int POS_PER_BLK = TPB / O_CH;      // 64

__global__ __launch_bounds__(TPB)
void qconv_kernel(const float* __restrict__ x,
                  const float* __restrict__ w,
                  float* __restrict__ out)
{
    const int tid  = threadIdx.x;
    const int lane = tid & 31;
    const int u    = lane & 7;               // o-channel AND x-trig qubit
    const int g    = lane >> 3;              // 0..3: this lane owns q=2g, 2g+1

    // --- this thread's sim position (x load issued FIRST)
    const int n_raw = blockIdx.x * POS_PER_BLK + (tid >> 3);
    const bool valid = (n_raw < N_POS);
    const int n   = valid ? n_raw : N_POS - 1;
    const int bb  = n / L_OUT;
    const int pos = n - bb * L_OUT;
    const float xv = x[(bb * 2 + (u >> 2)) * L_IN + pos + (u & 3)];

    // --- weight load: qubits 2g and 2g+1 of o-channel u, both layers.
    //     w layout (O, NQ, 2) -> float4 at index (u*NQ + 2g)/2 = u*4 + g
    const float4 wq4 = reinterpret_cast<const float4*>(w)[u * 4 + g];
    // wq4 = {p0[2g], p1[2g], p0[2g+1], p1[2g+1]}

    // x trig first (feeds DP step 0 of every lane via shfl)
    float cx, sx;
    __sincosf(xv, &sx, &cx);

    float c0a, s0a, c1a, s1a, c0b, s0b, c1b, s1b;
    __sincosf(wq4.x, &s0a, &c0a);            // layer0 @ q=2g
    __sincosf(wq4.y, &s1a, &c1a);            // layer1 @ q=2g
    __sincosf(wq4.z, &s0b, &c0b);            // layer0 @ q=2g+1
    __sincosf(wq4.w, &s1b, &c1b);            // layer1 @ q=2g+1

    // --- output indexing (overlaps trig latency)
    const int oo = n & 7;
    const int nh = n >> 3;                   // 0..1017
    const int hi = (nh >= L_OUT) ? 1 : 0;
    const int po = nh - hi * L_OUT;
    float* const optr = out + ((2 * u + hi) * O_CH + oo) * L_OUT + po;

    const int gbase = lane & 24;             // 8-lane group base within warp

    // --- 3-state transfer-matrix DP over the 8-qubit chain.
    // Coefficient (u, q): source lane u + 8*(q>>1), set a if (q&1)==0 else b.
    float v00 = 1.f, v01 = 1.f, v10 = 0.f;
#pragma unroll
    for (int q = 0; q < NQ; q++) {
        const int wsrc = u + ((q >> 1) << 3);
        const bool odd = (q & 1) != 0;
        const float c0 = __shfl_sync(0xffffffffu, odd ? c0b : c0a, wsrc);
        const float s0 = __shfl_sync(0xffffffffu, odd ? s0b : s0a, wsrc);
        const float c1 = __shfl_sync(0xffffffffu, odd ? c1b : c1a, wsrc);
        const float s1 = __shfl_sync(0xffffffffu, odd ? s1b : s1a, wsrc);
        const float cxq = __shfl_sync(0xffffffffu, cx, gbase + q);
        const float sxq = __shfl_sync(0xffffffffu, sx, gbase + q);
        const float C  = cxq * c0 - sxq * s0;       // cos(x+p0)
        const float S  = sxq * c0 + cxq * s0;       // sin(x+p0)
        const float uu  = -s1 * S;                  // -sin(p1) sin(x+p0)
        const float n00 = c1 * fmaf(v00, C, v10);
        const float n01 = c1 * fmaf(v10, C, v00);
        const float n10 = uu * v01;
        v00 = n00; v01 = n01; v10 = n10;
    }

    if (valid) *optr = v00 + v10;                   // boundary b_8 = 0
}

extern "C" void kernel_launch(void* const* d_in, const int* in_sizes, int n_in,
                              void* d_out, int out_size)
{
    const float* x = (const float*)d_in[0];
    const float* w = (const float*)d_in[1];
    float* out = (float*)d_out;
    const int blocks = (N_POS + POS_PER_BLK - 1) / POS_PER_BLK;   // 128
    qconv_kernel<<<blocks, TPB>>>(x, w, out);
}

// round 11
// speedup vs baseline: 1.0288x; 1.0288x over previous
#include <cuda_runtime.h>

// QConv1D quantum sim, FINAL (= R9, measured best 6.66us total / 4.93us kernel).
// Closed-form via Heisenberg conjugation: measurement Z^x8 pulled back through
// final-CZ (drops), layer-1 RYs (Z -> cosZ - sinX), CZ chain (X_q -> X_q Z_nbrs),
// evaluated on the product state from the fused RY(x)+RY(p0) layer. Surviving
// terms = independent sets of the 8-chain -> 3-state transfer-matrix DP.
// One THREAD per sim; warp-self-contained: NO smem, NO barriers.
//  - 8 consecutive lanes = one conv position x 8 out-channels (u = lane&7)
//  - x trig: one __sincosf per lane, exchanged with intra-group shfl
//  - weight trig: lane computes (o=u, q=g) and (o=u, q=g+4), g=lane>>3, both
//    layers (4 __sincosf); distributed by per-lane-src shfl.
constexpr int O_CH  = 8;
constexpr int NQ    = 8;
constexpr int L_IN  = 512;
constexpr int L_OUT = 509;
constexpr int B_SZ  = 16;
constexpr int N_POS = B_SZ * L_OUT;          // 8144 (multiple of 8)
constexpr int TPB   = 512;
constexpr int POS_PER_BLK = TPB / O_CH;      // 64

__global__ __launch_bounds__(TPB)
void qconv_kernel(const float* __restrict__ x,
                  const float* __restrict__ w,
                  float* __restrict__ out)
{
    const int tid  = threadIdx.x;
    const int lane = tid & 31;
    const int u    = lane & 7;               // o-channel AND x-trig qubit
    const int g    = lane >> 3;              // 0..3: weight-trig q slot

    // --- this thread's sim position (x load issued FIRST)
    const int n_raw = blockIdx.x * POS_PER_BLK + (tid >> 3);
    const bool valid = (n_raw < N_POS);
    const int n   = valid ? n_raw : N_POS - 1;
    const int bb  = n / L_OUT;
    const int pos = n - bb * L_OUT;
    const float xv = x[(bb * 2 + (u >> 2)) * L_IN + pos + (u & 3)];

    // --- weight loads for (o=u, q=g) and (o=u, q=g+4); w layout (O, NQ, 2)
    const float2 wa = reinterpret_cast<const float2*>(w)[u * NQ + g];      // {p0, p1} @ q=g
    const float2 wb = reinterpret_cast<const float2*>(w)[u * NQ + g + 4];  // {p0, p1} @ q=g+4

    float c0a, s0a, c1a, s1a, c0b, s0b, c1b, s1b, cx, sx;
    __sincosf(wa.x, &s0a, &c0a);
    __sincosf(wa.y, &s1a, &c1a);
    __sincosf(wb.x, &s0b, &c0b);
    __sincosf(wb.y, &s1b, &c1b);
    __sincosf(xv,   &sx,  &cx);

    // --- output indexing (overlaps trig latency)
    //     flat sim s = u*8144 + n reinterpreted by the reference reshape as
    //     [b'][p'][o']: oo = n&7 ; bo = 2u + (n>>3 >= 509)
    const int oo = n & 7;
    const int nh = n >> 3;                   // 0..1017
    const int hi = (nh >= L_OUT) ? 1 : 0;
    const int po = nh - hi * L_OUT;
    float* const optr = out + ((2 * u + hi) * O_CH + oo) * L_OUT + po;

    const int gbase = lane & 24;             // 8-lane group base within warp

    // --- 3-state transfer-matrix DP over the 8-qubit chain.
    // Coefficient (u, q) lives at lane u + 8*(q&3), set a for q<4 else b.
    float v00 = 1.f, v01 = 1.f, v10 = 0.f;
#pragma unroll
    for (int q = 0; q < NQ; q++) {
        const int wsrc = u + ((q & 3) << 3);
        const float c0 = __shfl_sync(0xffffffffu, (q < 4) ? c0a : c0b, wsrc);
        const float s0 = __shfl_sync(0xffffffffu, (q < 4) ? s0a : s0b, wsrc);
        const float c1 = __shfl_sync(0xffffffffu, (q < 4) ? c1a : c1b, wsrc);
        const float s1 = __shfl_sync(0xffffffffu, (q < 4) ? s1a : s1b, wsrc);
        const float cxq = __shfl_sync(0xffffffffu, cx, gbase + q);
        const float sxq = __shfl_sync(0xffffffffu, sx, gbase + q);
        const float C  = cxq * c0 - sxq * s0;       // cos(x+p0)
        const float S  = sxq * c0 + cxq * s0;       // sin(x+p0)
        const float uu  = -s1 * S;                  // -sin(p1) sin(x+p0)
        const float n00 = c1 * fmaf(v00, C, v10);
        const float n01 = c1 * fmaf(v10, C, v00);
        const float n10 = uu * v01;
        v00 = n00; v01 = n01; v10 = n10;
    }

    if (valid) *optr = v00 + v10;                   // boundary b_8 = 0
}

extern "C" void kernel_launch(void* const* d_in, const int* in_sizes, int n_in,
                              void* d_out, int out_size)
{
    const float* x = (const float*)d_in[0];
    const float* w = (const float*)d_in[1];
    float* out = (float*)d_out;
    const int blocks = (N_POS + POS_PER_BLK - 1) / POS_PER_BLK;   // 128
    qconv_kernel<<<blocks, TPB>>>(x, w, out);
}